// round 8
// baseline (speedup 1.0000x reference)
#include <cuda_runtime.h>
#include <cuda_bf16.h>
#include <stdint.h>

#define N_ROWS 32768
#define K_CODES 8192
#define D_DIM 256
#define THETA 6e-4f
#define CAP 5          // per-thread per-row candidate cap
#define ROWCAP 16      // per-row candidate cap
#define NTILES 64      // 8192 / 128
#define NCH (NTILES*4) // 64-d chunks

// smem layout (bytes): A [128 rows][528B], B 2 x [128 n][144B]
#define SM_A 0
#define A_STRIDE 528
#define SM_B 67584
#define B_STRIDE 144
#define B_BUF 18432
#define SMEM_TOTAL 104448
// merge scratch overlays A region after compute: per (row,owner) 48B
#define MG_STRIDE 48

__device__ __nv_bfloat16 g_xh[N_ROWS * D_DIM];
__device__ __nv_bfloat16 g_wh[K_CODES * D_DIM];
__device__ float  g_wsq[K_CODES];
__device__ float  g_xsq[N_ROWS];
__device__ int    g_ccnt[N_ROWS];
__device__ int    g_clist[N_ROWS * ROWCAP];
__device__ int    g_idx[N_ROWS];
__device__ double g_part[4096];

__device__ __forceinline__ uint32_t smem_u32(const void* p) {
    uint32_t a;
    asm("{ .reg .u64 t; cvta.to.shared.u64 t, %1; cvt.u32.u64 %0, t; }" : "=r"(a) : "l"(p));
    return a;
}
__device__ __forceinline__ void cp16(uint32_t dst, const void* src) {
    asm volatile("cp.async.cg.shared.global [%0], [%1], 16;" :: "r"(dst), "l"(src));
}
__device__ __forceinline__ void ldsm4(uint32_t* r, uint32_t a) {
    asm volatile("ldmatrix.sync.aligned.m8n8.x4.shared.b16 {%0,%1,%2,%3}, [%4];"
                 : "=r"(r[0]), "=r"(r[1]), "=r"(r[2]), "=r"(r[3]) : "r"(a));
}
#define MMA(d, a, b0, b1)                                                     \
    asm volatile("mma.sync.aligned.m16n8k16.row.col.f32.bf16.bf16.f32 "       \
                 "{%0,%1,%2,%3},{%4,%5,%6,%7},{%8,%9},{%0,%1,%2,%3};"         \
                 : "+f"((d)[0]), "+f"((d)[1]), "+f"((d)[2]), "+f"((d)[3])     \
                 : "r"((a)[0]), "r"((a)[1]), "r"((a)[2]), "r"((a)[3]),        \
                   "r"(b0), "r"(b1))

// ---------- auxiliary kernels ----------
__global__ __launch_bounds__(256)
void rowsq_kernel(const float* __restrict__ src, int nrows, int which) {
    int row = blockIdx.x * 256 + threadIdx.x;
    if (row >= nrows) return;
    const float4* p = (const float4*)(src + (size_t)row * D_DIM);
    float s0 = 0.f, s1 = 0.f, s2 = 0.f, s3 = 0.f;
    #pragma unroll 8
    for (int c = 0; c < D_DIM / 4; ++c) {
        float4 v = __ldg(p + c);
        s0 = __fmaf_rn(v.x, v.x, s0); s1 = __fmaf_rn(v.y, v.y, s1);
        s2 = __fmaf_rn(v.z, v.z, s2); s3 = __fmaf_rn(v.w, v.w, s3);
    }
    float r = __fadd_rn(__fadd_rn(s0, s1), __fadd_rn(s2, s3));
    if (which == 0) g_wsq[row] = r; else g_xsq[row] = r;
}

__global__ __launch_bounds__(256)
void splitH_kernel(const float* __restrict__ src, __nv_bfloat16* __restrict__ dh, int n4) {
    int i = blockIdx.x * 256 + threadIdx.x;
    if (i >= n4) return;
    float4 v = __ldg((const float4*)src + i);
    __nv_bfloat162 a, b;
    a.x = __float2bfloat16(v.x); a.y = __float2bfloat16(v.y);
    b.x = __float2bfloat16(v.z); b.y = __float2bfloat16(v.w);
    __nv_bfloat162* ph = (__nv_bfloat162*)dh;
    ph[i * 2] = a; ph[i * 2 + 1] = b;
}

// ---------- main HMMA screening kernel ----------
__global__ __launch_bounds__(256, 1)
void vq_mma_kernel() {
    extern __shared__ char sm[];
    const uint32_t smb = smem_u32(sm);
    const int tid = threadIdx.x;
    const int wid = tid >> 5, lane = tid & 31;
    const int wr = wid >> 1, wc = wid & 1;
    const int r0 = blockIdx.x * 128;

    // ldmatrix lane-address components
    const int arow = (lane & 7) + 8 * ((lane >> 3) & 1);
    const int ahalf = lane >> 4;
    const int brow = (lane & 7) + 8 * (lane >> 4);
    const int bhalf = (lane >> 3) & 1;

    // ---- A load (x_h rows r0..r0+127, stride 528B) ----
    #pragma unroll
    for (int it = 0; it < 16; ++it) {
        int idx = it * 256 + tid;        // 0..4095
        int row = idx >> 5, s = idx & 31;
        cp16(smb + SM_A + row * A_STRIDE + s * 16,
             g_xh + (size_t)(r0 + row) * D_DIM + s * 8);
    }
    auto loadB = [&](int m) {
        int t = m >> 2, c = m & 3;
        uint32_t bb = smb + SM_B + (m & 1) * B_BUF;
        #pragma unroll
        for (int it = 0; it < 4; ++it) {
            int idx = it * 256 + tid;    // 0..1023
            int n = idx >> 3, s = idx & 7;
            cp16(bb + n * B_STRIDE + s * 16,
                 g_wh + (size_t)(t * 128 + n) * D_DIM + c * 64 + s * 8);
        }
        asm volatile("cp.async.commit_group;" ::: "memory");
    };
    loadB(0);

    float acc[2][8][4];
    float bv[4] = {3.4e38f, 3.4e38f, 3.4e38f, 3.4e38f};
    int   cnt[4] = {0, 0, 0, 0};
    float cv[4][CAP];
    int   ci[4][CAP];

    for (int m = 0; m < NCH; ++m) {
        asm volatile("cp.async.wait_group 0;" ::: "memory");
        __syncthreads();
        if (m + 1 < NCH) loadB(m + 1);

        if ((m & 3) == 0) {
            #pragma unroll
            for (int mf = 0; mf < 2; ++mf)
                #pragma unroll
                for (int n = 0; n < 8; ++n)
                    #pragma unroll
                    for (int c = 0; c < 4; ++c) acc[mf][n][c] = 0.f;
        }

        // ---- compute chunk: 4 k-steps of 16 ----
        const int c4 = m & 3;
        const uint32_t bB = smb + SM_B + (m & 1) * B_BUF;
        #pragma unroll
        for (int ks = 0; ks < 4; ++ks) {
            uint32_t af[2][4], bf[4][4];
            #pragma unroll
            for (int mf = 0; mf < 2; ++mf)
                ldsm4(af[mf], smb + SM_A + (wr * 32 + mf * 16 + arow) * A_STRIDE
                              + c4 * 128 + ks * 32 + ahalf * 16);
            #pragma unroll
            for (int nb = 0; nb < 4; ++nb)
                ldsm4(bf[nb], bB + (wc * 64 + nb * 16 + brow) * B_STRIDE
                              + ks * 32 + bhalf * 16);
            #pragma unroll
            for (int mf = 0; mf < 2; ++mf)
                #pragma unroll
                for (int n = 0; n < 8; ++n)
                    MMA(acc[mf][n], af[mf], bf[n >> 1][2 * (n & 1)], bf[n >> 1][2 * (n & 1) + 1]);
        }

        // ---- tile epilogue: fused argmin screening ----
        if ((m & 3) == 3) {
            const int t = m >> 2;
            #pragma unroll
            for (int mf = 0; mf < 2; ++mf) {
                #pragma unroll
                for (int n = 0; n < 8; ++n) {
                    int col0 = t * 128 + wc * 64 + n * 8 + 2 * (lane & 3);
                    float2 w2 = __ldg((const float2*)&g_wsq[col0]);
                    #pragma unroll
                    for (int c = 0; c < 4; ++c) {
                        const int j = mf * 2 + (c >> 1);
                        float dv = __fmaf_rn(-2.f, acc[mf][n][c], (c & 1) ? w2.y : w2.x);
                        if (dv < bv[j] + THETA) {
                            int col = col0 + (c & 1);
                            int cj = cnt[j];
                            if (cj < CAP) { cv[j][cj] = dv; ci[j][cj] = col; cnt[j] = cj + 1; }
                            else cnt[j] = CAP + 1;       // sticky overflow
                            if (dv < bv[j]) {
                                bv[j] = dv;
                                if (cnt[j] <= CAP) {     // compact
                                    int k2 = 0;
                                    for (int e = 0; e < cnt[j]; ++e)
                                        if (cv[j][e] < dv + THETA) {
                                            cv[j][k2] = cv[j][e]; ci[j][k2] = ci[j][e]; ++k2;
                                        }
                                    cnt[j] = k2;
                                }
                            }
                        }
                    }
                }
            }
        }
    }
    __syncthreads();

    // ---- per-row merge via smem (overlay A region) ----
    const int owner = wc * 4 + (lane & 3);       // 8 owners per row
    #pragma unroll
    for (int j = 0; j < 4; ++j) {
        int row = wr * 32 + 8 * j + (lane >> 2);
        char* base = sm + (row * 8 + owner) * MG_STRIDE;
        *(float*)(base) = bv[j];
        *(int*)(base + 4) = cnt[j];
        #pragma unroll
        for (int e = 0; e < CAP; ++e) {
            *(int*)(base + 8 + e * 4) = (e < cnt[j] && cnt[j] <= CAP) ? ci[j][e] : 0;
            *(float*)(base + 28 + e * 4) = (e < cnt[j] && cnt[j] <= CAP) ? cv[j][e] : 3.4e38f;
        }
    }
    __syncthreads();

    if (tid < 128) {
        const int row = tid;
        float rm = 3.4e38f;
        #pragma unroll
        for (int o = 0; o < 8; ++o)
            rm = fminf(rm, *(float*)(sm + (row * 8 + o) * MG_STRIDE));
        int list[ROWCAP];
        int n = 0; bool ovf = false;
        for (int o = 0; o < 8; ++o) {
            char* base = sm + (row * 8 + o) * MG_STRIDE;
            int c = *(int*)(base + 4);
            if (c > CAP) { ovf = true; continue; }
            for (int e = 0; e < c; ++e) {
                float v = *(float*)(base + 28 + e * 4);
                if (v < rm + THETA) {
                    if (n < ROWCAP) list[n++] = *(int*)(base + 8 + e * 4);
                    else ovf = true;
                }
            }
        }
        int outc = ovf ? (ROWCAP + 1) : n;
        g_ccnt[r0 + row] = outc;
        for (int e = 0; e < n && e < ROWCAP; ++e)
            g_clist[(size_t)(r0 + row) * ROWCAP + e] = list[e];
    }
}

// ---------- exact rescue: ref fp32 sequence on candidates ----------
__global__ __launch_bounds__(256)
void rescue_kernel(const float* __restrict__ x, const float* __restrict__ w,
                   float* __restrict__ idxo) {
    int wid = threadIdx.x >> 5, lane = threadIdx.x & 31;
    int row = blockIdx.x * 8 + wid;
    if (row >= N_ROWS) return;
    int cnt = g_ccnt[row];
    if (cnt == 1) {
        if (lane == 0) {
            int bi = g_clist[(size_t)row * ROWCAP];
            g_idx[row] = bi;
            if (idxo) idxo[row] = (float)bi;
        }
        return;
    }
    float xsq = g_xsq[row];
    const float4* xr = (const float4*)(x + (size_t)row * D_DIM);
    float bestv = 3.4e38f;
    int besti = 0x7fffffff;
    auto exact = [&](int col) -> float {
        const float4* wr = (const float4*)(w + (size_t)col * D_DIM);
        float g = 0.f;
        #pragma unroll 8
        for (int q = 0; q < 64; ++q) {   // strictly sequential k order
            float4 xv = xr[q];
            float4 wv = __ldg(wr + q);
            g = __fmaf_rn(xv.x, wv.x, g); g = __fmaf_rn(xv.y, wv.y, g);
            g = __fmaf_rn(xv.z, wv.z, g); g = __fmaf_rn(xv.w, wv.w, g);
        }
        return __fadd_rn(__fsub_rn(xsq, __fmul_rn(2.f, g)), __ldg(&g_wsq[col]));
    };
    if (cnt <= ROWCAP) {
        if (lane < cnt) {
            int cix = g_clist[(size_t)row * ROWCAP + lane];
            bestv = exact(cix);
            besti = cix;
        }
    } else {
        for (int base = 0; base < K_CODES; base += 32) {
            int cix = base + lane;
            float dv = exact(cix);
            if (dv < bestv || (dv == bestv && cix < besti)) { bestv = dv; besti = cix; }
        }
    }
    #pragma unroll
    for (int mk = 16; mk > 0; mk >>= 1) {
        float vo = __shfl_xor_sync(0xffffffffu, bestv, mk);
        int io = __shfl_xor_sync(0xffffffffu, besti, mk);
        if (vo < bestv || (vo == bestv && io < besti)) { bestv = vo; besti = io; }
    }
    if (lane == 0) {
        g_idx[row] = besti;
        if (idxo) idxo[row] = (float)besti;
    }
}

// ---------- straight-through output + loss ----------
__global__ __launch_bounds__(256)
void loss_gather_kernel(const float* __restrict__ x, const float* __restrict__ w,
                        float* __restrict__ qst) {
    __shared__ double sred[256];
    int tid = threadIdx.x;
    double s = 0.0;
    size_t base = (size_t)blockIdx.x * 2048;
    #pragma unroll
    for (int i = 0; i < 2; ++i) {
        size_t e = base + (size_t)tid * 4 + (size_t)i * 1024;
        int row = (int)(e >> 8);
        int d = (int)(e & 255);
        int idx = g_idx[row];
        float4 xv = *(const float4*)(x + e);
        float4 qv = __ldg((const float4*)(w + (size_t)idx * D_DIM + d));
        float4 o;
        o.x = __fadd_rn(xv.x, __fsub_rn(qv.x, xv.x));
        o.y = __fadd_rn(xv.y, __fsub_rn(qv.y, xv.y));
        o.z = __fadd_rn(xv.z, __fsub_rn(qv.z, xv.z));
        o.w = __fadd_rn(xv.w, __fsub_rn(qv.w, xv.w));
        *(float4*)(qst + e) = o;
        float dx;
        dx = __fsub_rn(xv.x, qv.x); s += (double)__fmul_rn(dx, dx);
        dx = __fsub_rn(xv.y, qv.y); s += (double)__fmul_rn(dx, dx);
        dx = __fsub_rn(xv.z, qv.z); s += (double)__fmul_rn(dx, dx);
        dx = __fsub_rn(xv.w, qv.w); s += (double)__fmul_rn(dx, dx);
    }
    sred[tid] = s;
    __syncthreads();
    for (int st = 128; st > 0; st >>= 1) {
        if (tid < st) sred[tid] += sred[tid + st];
        __syncthreads();
    }
    if (tid == 0) g_part[blockIdx.x] = sred[0];
}

__global__ __launch_bounds__(256)
void finalize_kernel(float* __restrict__ sc) {
    __shared__ double sred[256];
    int tid = threadIdx.x;
    double s = 0.0;
    for (int j = tid; j < 4096; j += 256) s += g_part[j];
    sred[tid] = s;
    __syncthreads();
    for (int st = 128; st > 0; st >>= 1) {
        if (tid < st) sred[tid] += sred[tid + st];
        __syncthreads();
    }
    if (tid == 0 && sc) {
        double mean = sred[0] / (double)((size_t)N_ROWS * D_DIM);
        float M = (float)mean;
        float commit = __fmul_rn(M, 0.25f);
        sc[0] = commit;
        sc[1] = M;
        sc[2] = __fadd_rn(commit, M);
    }
}

extern "C" void kernel_launch(void* const* d_in, const int* in_sizes, int n_in,
                              void* d_out, int out_size) {
    const float* x = (const float*)d_in[0];
    const float* w = (const float*)d_in[1];
    if (n_in >= 2 && in_sizes[0] == K_CODES * D_DIM && in_sizes[1] == N_ROWS * D_DIM) {
        const float* t = x; x = w; w = t;
    }

    float* out = (float*)d_out;
    const int ND = N_ROWS * D_DIM;
    float* qst = out;
    float* idxo = (out_size >= ND + N_ROWS) ? out + ND : nullptr;
    float* sc = (out_size >= ND + N_ROWS + 3) ? out + ND + N_ROWS : nullptr;

    static int setup = 0;
    if (!setup) {
        cudaFuncSetAttribute(vq_mma_kernel,
                             cudaFuncAttributeMaxDynamicSharedMemorySize, SMEM_TOTAL);
        setup = 1;
    }

    __nv_bfloat16 *xh, *wh;
    cudaGetSymbolAddress((void**)&xh, g_xh);
    cudaGetSymbolAddress((void**)&wh, g_wh);

    rowsq_kernel<<<K_CODES / 256, 256>>>(w, K_CODES, 0);
    rowsq_kernel<<<N_ROWS / 256, 256>>>(x, N_ROWS, 1);
    splitH_kernel<<<(N_ROWS * D_DIM / 4) / 256, 256>>>(x, xh, N_ROWS * D_DIM / 4);
    splitH_kernel<<<(K_CODES * D_DIM / 4) / 256, 256>>>(w, wh, K_CODES * D_DIM / 4);
    vq_mma_kernel<<<N_ROWS / 128, 256, SMEM_TOTAL>>>();
    rescue_kernel<<<N_ROWS / 8, 256>>>(x, w, idxo);
    loss_gather_kernel<<<4096, 256>>>(x, w, qst);
    finalize_kernel<<<1, 256>>>(sc);
}

// round 9
// speedup vs baseline: 1.0935x; 1.0935x over previous
#include <cuda_runtime.h>
#include <cuda_bf16.h>
#include <stdint.h>

#define N_ROWS 32768
#define K_CODES 8192
#define D_DIM 256
#define THETA 6e-4f
#define CAP 5          // per-thread per-row candidate cap
#define ROWCAP 16      // per-row candidate cap
#define NTILES 64      // 8192 / 128
#define NCH (NTILES*4) // 64-d chunks

// smem layout (bytes): A [128 rows][528B], B 2 x [128 n][144B]
#define SM_A 0
#define A_STRIDE 528
#define SM_B 67584
#define B_STRIDE 144
#define B_BUF 18432
#define SMEM_TOTAL 104448
// merge scratch overlays A region after compute: per (row,owner) 48B
#define MG_STRIDE 48

__device__ __nv_bfloat16 g_xh[N_ROWS * D_DIM];
__device__ __nv_bfloat16 g_wh[K_CODES * D_DIM];
__device__ float  g_wsq[K_CODES];
__device__ float  g_xsq[N_ROWS];
__device__ int    g_ccnt[N_ROWS];
__device__ int    g_clist[N_ROWS * ROWCAP];
__device__ int    g_idx[N_ROWS];
__device__ double g_part[4096];

__device__ __forceinline__ uint32_t smem_u32(const void* p) {
    uint32_t a;
    asm("{ .reg .u64 t; cvta.to.shared.u64 t, %1; cvt.u32.u64 %0, t; }" : "=r"(a) : "l"(p));
    return a;
}
__device__ __forceinline__ void cp16(uint32_t dst, const void* src) {
    asm volatile("cp.async.cg.shared.global [%0], [%1], 16;" :: "r"(dst), "l"(src));
}
__device__ __forceinline__ void ldsm4(uint32_t* r, uint32_t a) {
    asm volatile("ldmatrix.sync.aligned.m8n8.x4.shared.b16 {%0,%1,%2,%3}, [%4];"
                 : "=r"(r[0]), "=r"(r[1]), "=r"(r[2]), "=r"(r[3]) : "r"(a));
}
#define MMA(d, a, b0, b1)                                                     \
    asm volatile("mma.sync.aligned.m16n8k16.row.col.f32.bf16.bf16.f32 "       \
                 "{%0,%1,%2,%3},{%4,%5,%6,%7},{%8,%9},{%0,%1,%2,%3};"         \
                 : "+f"((d)[0]), "+f"((d)[1]), "+f"((d)[2]), "+f"((d)[3])     \
                 : "r"((a)[0]), "r"((a)[1]), "r"((a)[2]), "r"((a)[3]),        \
                   "r"(b0), "r"(b1))

// ---------- auxiliary kernels ----------
__global__ __launch_bounds__(256)
void rowsq_kernel(const float* __restrict__ src, int nrows, int which) {
    int row = blockIdx.x * 256 + threadIdx.x;
    if (row >= nrows) return;
    const float4* p = (const float4*)(src + (size_t)row * D_DIM);
    float s0 = 0.f, s1 = 0.f, s2 = 0.f, s3 = 0.f;
    #pragma unroll 8
    for (int c = 0; c < D_DIM / 4; ++c) {
        float4 v = __ldg(p + c);
        s0 = __fmaf_rn(v.x, v.x, s0); s1 = __fmaf_rn(v.y, v.y, s1);
        s2 = __fmaf_rn(v.z, v.z, s2); s3 = __fmaf_rn(v.w, v.w, s3);
    }
    float r = __fadd_rn(__fadd_rn(s0, s1), __fadd_rn(s2, s3));
    if (which == 0) g_wsq[row] = r; else g_xsq[row] = r;
}

__global__ __launch_bounds__(256)
void splitH_kernel(const float* __restrict__ src, __nv_bfloat16* __restrict__ dh, int n4) {
    int i = blockIdx.x * 256 + threadIdx.x;
    if (i >= n4) return;
    float4 v = __ldg((const float4*)src + i);
    __nv_bfloat162 a, b;
    a.x = __float2bfloat16(v.x); a.y = __float2bfloat16(v.y);
    b.x = __float2bfloat16(v.z); b.y = __float2bfloat16(v.w);
    __nv_bfloat162* ph = (__nv_bfloat162*)dh;
    ph[i * 2] = a; ph[i * 2 + 1] = b;
}

// ---------- main HMMA screening kernel ----------
__global__ __launch_bounds__(256, 1)
void vq_mma_kernel() {
    extern __shared__ char sm[];
    const uint32_t smb = smem_u32(sm);
    const int tid = threadIdx.x;
    const int wid = tid >> 5, lane = tid & 31;
    const int wr = wid >> 1, wc = wid & 1;
    const int r0 = blockIdx.x * 128;

    // ldmatrix lane-address components
    const int arow = (lane & 7) + 8 * ((lane >> 3) & 1);
    const int ahalf = lane >> 4;
    const int brow = (lane & 7) + 8 * (lane >> 4);
    const int bhalf = (lane >> 3) & 1;

    // ---- A load (x_h rows r0..r0+127, stride 528B) ----
    #pragma unroll
    for (int it = 0; it < 16; ++it) {
        int idx = it * 256 + tid;        // 0..4095
        int row = idx >> 5, s = idx & 31;
        cp16(smb + SM_A + row * A_STRIDE + s * 16,
             g_xh + (size_t)(r0 + row) * D_DIM + s * 8);
    }
    auto loadB = [&](int m) {
        int t = m >> 2, c = m & 3;
        uint32_t bb = smb + SM_B + (m & 1) * B_BUF;
        #pragma unroll
        for (int it = 0; it < 4; ++it) {
            int idx = it * 256 + tid;    // 0..1023
            int n = idx >> 3, s = idx & 7;
            cp16(bb + n * B_STRIDE + s * 16,
                 g_wh + (size_t)(t * 128 + n) * D_DIM + c * 64 + s * 8);
        }
        asm volatile("cp.async.commit_group;" ::: "memory");
    };
    loadB(0);

    float acc[2][8][4];
    float bv[4] = {3.4e38f, 3.4e38f, 3.4e38f, 3.4e38f};
    int   cnt[4] = {0, 0, 0, 0};
    float cv[4][CAP];
    int   ci[4][CAP];

    for (int m = 0; m < NCH; ++m) {
        asm volatile("cp.async.wait_group 0;" ::: "memory");
        __syncthreads();
        if (m + 1 < NCH) loadB(m + 1);

        if ((m & 3) == 0) {
            #pragma unroll
            for (int mf = 0; mf < 2; ++mf)
                #pragma unroll
                for (int n = 0; n < 8; ++n)
                    #pragma unroll
                    for (int c = 0; c < 4; ++c) acc[mf][n][c] = 0.f;
        }

        // ---- compute chunk: 4 k-steps of 16 ----
        const int c4 = m & 3;
        const uint32_t bB = smb + SM_B + (m & 1) * B_BUF;
        #pragma unroll
        for (int ks = 0; ks < 4; ++ks) {
            uint32_t af[2][4], bf[4][4];
            #pragma unroll
            for (int mf = 0; mf < 2; ++mf)
                ldsm4(af[mf], smb + SM_A + (wr * 32 + mf * 16 + arow) * A_STRIDE
                              + c4 * 128 + ks * 32 + ahalf * 16);
            #pragma unroll
            for (int nb = 0; nb < 4; ++nb)
                ldsm4(bf[nb], bB + (wc * 64 + nb * 16 + brow) * B_STRIDE
                              + ks * 32 + bhalf * 16);
            #pragma unroll
            for (int mf = 0; mf < 2; ++mf)
                #pragma unroll
                for (int n = 0; n < 8; ++n)
                    MMA(acc[mf][n], af[mf], bf[n >> 1][2 * (n & 1)], bf[n >> 1][2 * (n & 1) + 1]);
        }

        // ---- tile epilogue: fused argmin screening (compact-on-insert) ----
        if ((m & 3) == 3) {
            const int t = m >> 2;
            #pragma unroll
            for (int mf = 0; mf < 2; ++mf) {
                #pragma unroll
                for (int n = 0; n < 8; ++n) {
                    int col0 = t * 128 + wc * 64 + n * 8 + 2 * (lane & 3);
                    float2 w2 = __ldg((const float2*)&g_wsq[col0]);
                    #pragma unroll
                    for (int c = 0; c < 4; ++c) {
                        const int j = mf * 2 + (c >> 1);
                        float dv = __fmaf_rn(-2.f, acc[mf][n][c], (c & 1) ? w2.y : w2.x);
                        if (dv < bv[j] + THETA) {
                            if (dv < bv[j]) bv[j] = dv;
                            if (cnt[j] <= CAP) {
                                // prune list against the CURRENT min, then insert
                                int k2 = 0;
                                #pragma unroll
                                for (int e = 0; e < CAP; ++e)
                                    if (e < cnt[j] && cv[j][e] < bv[j] + THETA) {
                                        cv[j][k2] = cv[j][e]; ci[j][k2] = ci[j][e]; ++k2;
                                    }
                                if (k2 < CAP) {
                                    cv[j][k2] = dv; ci[j][k2] = col0 + (c & 1);
                                    cnt[j] = k2 + 1;
                                } else cnt[j] = CAP + 1;  // genuinely full: sticky
                            }
                        }
                    }
                }
            }
        }
    }
    __syncthreads();

    // ---- per-row merge via smem (overlay A region) ----
    const int owner = wc * 4 + (lane & 3);       // 8 owners per row
    #pragma unroll
    for (int j = 0; j < 4; ++j) {
        int row = wr * 32 + 8 * j + (lane >> 2);
        char* base = sm + (row * 8 + owner) * MG_STRIDE;
        *(float*)(base) = bv[j];
        *(int*)(base + 4) = cnt[j];
        #pragma unroll
        for (int e = 0; e < CAP; ++e) {
            *(int*)(base + 8 + e * 4) = (e < cnt[j] && cnt[j] <= CAP) ? ci[j][e] : 0;
            *(float*)(base + 28 + e * 4) = (e < cnt[j] && cnt[j] <= CAP) ? cv[j][e] : 3.4e38f;
        }
    }
    __syncthreads();

    if (tid < 128) {
        const int row = tid;
        float rm = 3.4e38f;
        #pragma unroll
        for (int o = 0; o < 8; ++o)
            rm = fminf(rm, *(float*)(sm + (row * 8 + o) * MG_STRIDE));
        int list[ROWCAP];
        int n = 0; bool ovf = false;
        for (int o = 0; o < 8; ++o) {
            char* base = sm + (row * 8 + o) * MG_STRIDE;
            int c = *(int*)(base + 4);
            if (c > CAP) { ovf = true; continue; }
            for (int e = 0; e < c; ++e) {
                float v = *(float*)(base + 28 + e * 4);
                if (v < rm + THETA) {
                    if (n < ROWCAP) list[n++] = *(int*)(base + 8 + e * 4);
                    else ovf = true;
                }
            }
        }
        int outc = ovf ? (ROWCAP + 1) : n;
        g_ccnt[r0 + row] = outc;
        for (int e = 0; e < n && e < ROWCAP; ++e)
            g_clist[(size_t)(r0 + row) * ROWCAP + e] = list[e];
    }
}

// ---------- exact rescue: ref fp32 sequence on candidates ----------
__global__ __launch_bounds__(256)
void rescue_kernel(const float* __restrict__ x, const float* __restrict__ w,
                   float* __restrict__ idxo) {
    int wid = threadIdx.x >> 5, lane = threadIdx.x & 31;
    int row = blockIdx.x * 8 + wid;
    if (row >= N_ROWS) return;
    int cnt = g_ccnt[row];
    if (cnt == 1) {
        if (lane == 0) {
            int bi = g_clist[(size_t)row * ROWCAP];
            g_idx[row] = bi;
            if (idxo) idxo[row] = (float)bi;
        }
        return;
    }
    float xsq = g_xsq[row];
    const float4* xr = (const float4*)(x + (size_t)row * D_DIM);
    float bestv = 3.4e38f;
    int besti = 0x7fffffff;
    auto exact = [&](int col) -> float {
        const float4* wr = (const float4*)(w + (size_t)col * D_DIM);
        float g = 0.f;
        #pragma unroll 8
        for (int q = 0; q < 64; ++q) {   // strictly sequential k order
            float4 xv = xr[q];
            float4 wv = __ldg(wr + q);
            g = __fmaf_rn(xv.x, wv.x, g); g = __fmaf_rn(xv.y, wv.y, g);
            g = __fmaf_rn(xv.z, wv.z, g); g = __fmaf_rn(xv.w, wv.w, g);
        }
        return __fadd_rn(__fsub_rn(xsq, __fmul_rn(2.f, g)), __ldg(&g_wsq[col]));
    };
    if (cnt <= ROWCAP) {
        if (lane < cnt) {
            int cix = g_clist[(size_t)row * ROWCAP + lane];
            bestv = exact(cix);
            besti = cix;
        }
    } else {
        for (int base = 0; base < K_CODES; base += 32) {
            int cix = base + lane;
            float dv = exact(cix);
            if (dv < bestv || (dv == bestv && cix < besti)) { bestv = dv; besti = cix; }
        }
    }
    #pragma unroll
    for (int mk = 16; mk > 0; mk >>= 1) {
        float vo = __shfl_xor_sync(0xffffffffu, bestv, mk);
        int io = __shfl_xor_sync(0xffffffffu, besti, mk);
        if (vo < bestv || (vo == bestv && io < besti)) { bestv = vo; besti = io; }
    }
    if (lane == 0) {
        g_idx[row] = besti;
        if (idxo) idxo[row] = (float)besti;
    }
}

// ---------- straight-through output + loss ----------
__global__ __launch_bounds__(256)
void loss_gather_kernel(const float* __restrict__ x, const float* __restrict__ w,
                        float* __restrict__ qst) {
    __shared__ double sred[256];
    int tid = threadIdx.x;
    double s = 0.0;
    size_t base = (size_t)blockIdx.x * 2048;
    #pragma unroll
    for (int i = 0; i < 2; ++i) {
        size_t e = base + (size_t)tid * 4 + (size_t)i * 1024;
        int row = (int)(e >> 8);
        int d = (int)(e & 255);
        int idx = g_idx[row];
        float4 xv = *(const float4*)(x + e);
        float4 qv = __ldg((const float4*)(w + (size_t)idx * D_DIM + d));
        float4 o;
        o.x = __fadd_rn(xv.x, __fsub_rn(qv.x, xv.x));
        o.y = __fadd_rn(xv.y, __fsub_rn(qv.y, xv.y));
        o.z = __fadd_rn(xv.z, __fsub_rn(qv.z, xv.z));
        o.w = __fadd_rn(xv.w, __fsub_rn(qv.w, xv.w));
        *(float4*)(qst + e) = o;
        float dx;
        dx = __fsub_rn(xv.x, qv.x); s += (double)__fmul_rn(dx, dx);
        dx = __fsub_rn(xv.y, qv.y); s += (double)__fmul_rn(dx, dx);
        dx = __fsub_rn(xv.z, qv.z); s += (double)__fmul_rn(dx, dx);
        dx = __fsub_rn(xv.w, qv.w); s += (double)__fmul_rn(dx, dx);
    }
    sred[tid] = s;
    __syncthreads();
    for (int st = 128; st > 0; st >>= 1) {
        if (tid < st) sred[tid] += sred[tid + st];
        __syncthreads();
    }
    if (tid == 0) g_part[blockIdx.x] = sred[0];
}

__global__ __launch_bounds__(256)
void finalize_kernel(float* __restrict__ sc) {
    __shared__ double sred[256];
    int tid = threadIdx.x;
    double s = 0.0;
    for (int j = tid; j < 4096; j += 256) s += g_part[j];
    sred[tid] = s;
    __syncthreads();
    for (int st = 128; st > 0; st >>= 1) {
        if (tid < st) sred[tid] += sred[tid + st];
        __syncthreads();
    }
    if (tid == 0 && sc) {
        double mean = sred[0] / (double)((size_t)N_ROWS * D_DIM);
        float M = (float)mean;
        float commit = __fmul_rn(M, 0.25f);
        sc[0] = commit;
        sc[1] = M;
        sc[2] = __fadd_rn(commit, M);
    }
}

extern "C" void kernel_launch(void* const* d_in, const int* in_sizes, int n_in,
                              void* d_out, int out_size) {
    const float* x = (const float*)d_in[0];
    const float* w = (const float*)d_in[1];
    if (n_in >= 2 && in_sizes[0] == K_CODES * D_DIM && in_sizes[1] == N_ROWS * D_DIM) {
        const float* t = x; x = w; w = t;
    }

    float* out = (float*)d_out;
    const int ND = N_ROWS * D_DIM;
    float* qst = out;
    float* idxo = (out_size >= ND + N_ROWS) ? out + ND : nullptr;
    float* sc = (out_size >= ND + N_ROWS + 3) ? out + ND + N_ROWS : nullptr;

    static int setup = 0;
    if (!setup) {
        cudaFuncSetAttribute(vq_mma_kernel,
                             cudaFuncAttributeMaxDynamicSharedMemorySize, SMEM_TOTAL);
        setup = 1;
    }

    __nv_bfloat16 *xh, *wh;
    cudaGetSymbolAddress((void**)&xh, g_xh);
    cudaGetSymbolAddress((void**)&wh, g_wh);

    rowsq_kernel<<<K_CODES / 256, 256>>>(w, K_CODES, 0);
    rowsq_kernel<<<N_ROWS / 256, 256>>>(x, N_ROWS, 1);
    splitH_kernel<<<(N_ROWS * D_DIM / 4) / 256, 256>>>(x, xh, N_ROWS * D_DIM / 4);
    splitH_kernel<<<(K_CODES * D_DIM / 4) / 256, 256>>>(w, wh, K_CODES * D_DIM / 4);
    vq_mma_kernel<<<N_ROWS / 128, 256, SMEM_TOTAL>>>();
    rescue_kernel<<<N_ROWS / 8, 256>>>(x, w, idxo);
    loss_gather_kernel<<<4096, 256>>>(x, w, qst);
    finalize_kernel<<<1, 256>>>(sc);
}